// round 1
// baseline (speedup 1.0000x reference)
#include <cuda_runtime.h>
#include <cstdint>

#define HH 96
#define WW 96
#define HW (HH*WW)
#define NB 8
#define SLICES 8
#define NBLK (NB*2*SLICES)    // 128 blocks
#define NTHR 256
#define PTS_PER_BLK (HW/SLICES)  // 1152

__device__ float g_partials[NBLK];
__device__ int   g_done = 0;

__global__ void __launch_bounds__(NTHR)
hausdorff_kernel(const float* __restrict__ pred,
                 const float* __restrict__ targ,
                 float* __restrict__ out)
{
    __shared__ uint32_t s_tgt[HH * 4];
    __shared__ uint32_t s_src[HH * 4];
    __shared__ float    s_red[NTHR / 32];

    const int blk   = blockIdx.x;
    const int slice = blk & (SLICES - 1);
    const int nd    = blk >> 3;        // n*2 + dir
    const int dir   = nd & 1;
    const int n     = nd >> 1;

    const int tid  = threadIdx.x;
    const int lane = tid & 31;
    const int warp = tid >> 5;

    // zero pad word 3 of every row (96 cols = exactly 3 words; word 3 stays 0)
    if (tid < HH) { s_tgt[tid * 4 + 3] = 0u; s_src[tid * 4 + 3] = 0u; }

    const float* pA = pred + n * HW;
    const float* pB = targ + n * HW;

    // Build bit masks: task = row*3 + wordIdx (288 tasks), one warp per task.
    // mask bit = (rintf(x) > 0.5f)  -- rintf is round-half-to-even, matching jnp.round.
    for (int t = warp; t < HH * 3; t += NTHR / 32) {
        const int row = t / 3;
        const int w   = t - row * 3;
        const int idx = row * WW + w * 32 + lane;
        const float a = pA[idx];
        const float b = pB[idx];
        const uint32_t wa = __ballot_sync(0xFFFFFFFFu, rintf(a) > 0.5f);
        const uint32_t wb = __ballot_sync(0xFFFFFFFFu, rintf(b) > 0.5f);
        if (lane == 0) {
            uint32_t src, tgt;
            if (dir == 0) { src = wa & ~wb; tgt = wb; }   // A\B vs B
            else          { src = wb & ~wa; tgt = wa; }   // B\A vs A
            s_src[row * 4 + w] = src;
            s_tgt[row * 4 + w] = tgt;
        }
    }
    __syncthreads();

    float lmax = -1.0f;   // sentinel: stays negative iff this slice has no src points

    const int pend = (slice + 1) * PTS_PER_BLK;
    for (int p = slice * PTS_PER_BLK + tid; p < pend; p += NTHR) {
        const int r = p / WW;
        const int c = p - r * WW;
        const uint32_t sw = s_src[r * 4 + (c >> 5)];
        if (!((sw >> (c & 31)) & 1u)) continue;

        int best = 0x7FFFFFFF;            // squared integer distance
        const int k0 = c >> 5;
        const int s  = c & 31;
        const uint32_t maskR = 0xFFFFFFFFu << s;   // bits >= c within word k0
        const uint32_t maskL = (2u << s) - 1u;     // bits <= c within word k0

        // Expanding ring over rows; exact because row(|dy|=d) contributes >= d^2.
        for (int d = 0; d < HH; ++d) {
            const int dd = d * d;
            if (dd >= best) break;
            #pragma unroll
            for (int side = 0; side < 2; ++side) {
                if (side && d == 0) continue;
                const int y = side ? (r + d) : (r - d);
                if ((unsigned)y >= (unsigned)HH) continue;
                const uint32_t* w = &s_tgt[y * 4];

                // nearest set bit to column c in this 96-bit row
                int dx = 10000;
                uint32_t m = w[k0] & maskR;                        // right side
                if (m) dx = (k0 << 5) + (__ffs(m) - 1) - c;
                else if (k0 < 2 && w[k0 + 1]) dx = ((k0 + 1) << 5) + (__ffs(w[k0 + 1]) - 1) - c;
                else if (k0 < 1 && w[2])      dx = 64 + (__ffs(w[2]) - 1) - c;

                int dl = 10000;                                    // left side
                m = w[k0] & maskL;
                if (m) dl = c - ((k0 << 5) + 31 - __clz(m));
                else if (k0 > 0 && w[k0 - 1]) dl = c - (((k0 - 1) << 5) + 31 - __clz(w[k0 - 1]));
                else if (k0 > 1 && w[0])      dl = c - (31 - __clz(w[0]));

                dx = min(dx, dl);
                if (dx < WW) best = min(best, dd + dx * dx);
            }
        }
        const float pd = (best == 0x7FFFFFFF) ? 1e9f
                                              : sqrtf((float)best) * (1.0f / 96.0f);
        lmax = fmaxf(lmax, pd);
    }

    // block max reduction
    for (int off = 16; off; off >>= 1)
        lmax = fmaxf(lmax, __shfl_xor_sync(0xFFFFFFFFu, lmax, off));
    if (lane == 0) s_red[warp] = lmax;
    __syncthreads();

    if (tid == 0) {
        float bm = s_red[0];
        #pragma unroll
        for (int i = 1; i < NTHR / 32; ++i) bm = fmaxf(bm, s_red[i]);
        g_partials[blk] = bm;
        __threadfence();
        const int prev = atomicAdd(&g_done, 1);
        if (prev == NBLK - 1) {
            __threadfence();
            float sum = 0.0f;
            for (int nn = 0; nn < NB; ++nn) {
                float dA = -1.0f, dB = -1.0f;
                for (int sl = 0; sl < SLICES; ++sl) {
                    dA = fmaxf(dA, g_partials[(nn * 2 + 0) * SLICES + sl]);
                    dB = fmaxf(dB, g_partials[(nn * 2 + 1) * SLICES + sl]);
                }
                dA = fmaxf(dA, 0.0f);   // empty src set -> 0 (matches reference)
                dB = fmaxf(dB, 0.0f);
                sum += fmaxf(dA, dB);
            }
            out[0] = sum * (1.0f / NB);
            g_done = 0;                  // reset for next graph replay
        }
    }
}

extern "C" void kernel_launch(void* const* d_in, const int* in_sizes, int n_in,
                              void* d_out, int out_size)
{
    (void)in_sizes; (void)n_in; (void)out_size;
    const float* pred = (const float*)d_in[0];
    const float* targ = (const float*)d_in[1];
    hausdorff_kernel<<<NBLK, NTHR>>>(pred, targ, (float*)d_out);
}

// round 2
// speedup vs baseline: 1.6040x; 1.6040x over previous
#include <cuda_runtime.h>
#include <cstdint>

#define HH 96
#define WW 96
#define HW (HH*WW)
#define NB 8
#define SLICES 8
#define NBLK (NB*2*SLICES)    // 128 blocks
#define NTHR 256
#define PTS_PER_BLK (HW/SLICES)  // 1152

__device__ float g_partials[NBLK];
__device__ int   g_done = 0;

__global__ void __launch_bounds__(NTHR)
hausdorff_kernel(const float* __restrict__ pred,
                 const float* __restrict__ targ,
                 float* __restrict__ out)
{
    // masks: stride 4 words per row, words 0..2 used (word 3 never read)
    __shared__ uint32_t s_A[HH * 4];
    __shared__ uint32_t s_B[HH * 4];
    __shared__ float    s_red[NTHR / 32];
    __shared__ float    s_fin[NBLK];
    __shared__ int      s_last;

    const int blk   = blockIdx.x;
    const int slice = blk & (SLICES - 1);
    const int nd    = blk >> 3;        // n*2 + dir
    const int dir   = nd & 1;
    const int n     = nd >> 1;

    const int tid  = threadIdx.x;
    const int lane = tid & 31;
    const int warp = tid >> 5;

    // zero mask words (only 0..2 per row matter, zero all 4 for simplicity)
    #pragma unroll
    for (int i = tid; i < HH * 4; i += NTHR) { s_A[i] = 0u; s_B[i] = 0u; }
    if (tid == 0) s_last = 0;
    __syncthreads();

    const float4* pA4 = (const float4*)(pred + n * HW);
    const float4* pB4 = (const float4*)(targ + n * HW);

    // Build bit masks: 2304 float4 per image, 9 per thread, all loads independent.
    // inputs are uniform [0,1): round(x) > 0.5  <=>  x > 0.5f  (0.5 ties -> 0)
    #pragma unroll
    for (int k = 0; k < 9; ++k) {
        const int idx4 = tid + k * NTHR;          // float4 index
        const float4 a = pA4[idx4];
        const float4 b = pB4[idx4];
        const int lw    = idx4 >> 3;              // linear 32-bit word index [0,288)
        const int row   = lw / 3;
        const int widx  = row * 4 + (lw - row * 3);
        const int shift = (idx4 & 7) * 4;
        uint32_t nibA = (a.x > 0.5f ? 1u : 0u) | (a.y > 0.5f ? 2u : 0u)
                      | (a.z > 0.5f ? 4u : 0u) | (a.w > 0.5f ? 8u : 0u);
        uint32_t nibB = (b.x > 0.5f ? 1u : 0u) | (b.y > 0.5f ? 2u : 0u)
                      | (b.z > 0.5f ? 4u : 0u) | (b.w > 0.5f ? 8u : 0u);
        if (nibA) atomicOr(&s_A[widx], nibA << shift);
        if (nibB) atomicOr(&s_B[widx], nibB << shift);
    }
    __syncthreads();

    // dir 0: src = A & ~B, tgt = B;  dir 1: src = B & ~A, tgt = A
    const uint32_t* s_srcp = dir ? s_B : s_A;
    const uint32_t* s_tgt  = dir ? s_A : s_B;

    float lmax = -1.0f;   // stays negative iff this slice has no src points

    const int pend = (slice + 1) * PTS_PER_BLK;
    for (int p = slice * PTS_PER_BLK + tid; p < pend; p += NTHR) {
        const int r = p / WW;
        const int c = p - r * WW;
        const int k0 = c >> 5;
        const uint32_t sw = s_srcp[r * 4 + k0] & ~s_tgt[r * 4 + k0];
        if (!((sw >> (c & 31)) & 1u)) continue;

        int best = 0x7FFFFFFF;            // squared integer distance
        const int s  = c & 31;
        const uint32_t maskR = 0xFFFFFFFFu << s;   // bits >= c within word k0
        const uint32_t maskL = (2u << s) - 1u;     // bits <= c within word k0

        // Expanding ring over rows; exact because row(|dy|=d) contributes >= d^2.
        for (int d = 0; d < HH; ++d) {
            const int dd = d * d;
            if (dd >= best) break;
            #pragma unroll
            for (int side = 0; side < 2; ++side) {
                if (side && d == 0) continue;
                const int y = side ? (r + d) : (r - d);
                if ((unsigned)y >= (unsigned)HH) continue;
                const uint32_t* w = &s_tgt[y * 4];

                // nearest set bit to column c in this 96-bit row
                int dx = 10000;
                uint32_t m = w[k0] & maskR;                        // right side
                if (m) dx = (k0 << 5) + (__ffs(m) - 1) - c;
                else if (k0 < 2 && w[k0 + 1]) dx = ((k0 + 1) << 5) + (__ffs(w[k0 + 1]) - 1) - c;
                else if (k0 < 1 && w[2])      dx = 64 + (__ffs(w[2]) - 1) - c;

                int dl = 10000;                                    // left side
                m = w[k0] & maskL;
                if (m) dl = c - ((k0 << 5) + 31 - __clz(m));
                else if (k0 > 0 && w[k0 - 1]) dl = c - (((k0 - 1) << 5) + 31 - __clz(w[k0 - 1]));
                else if (k0 > 1 && w[0])      dl = c - (31 - __clz(w[0]));

                dx = min(dx, dl);
                if (dx < WW) best = min(best, dd + dx * dx);
            }
        }
        const float pd = (best == 0x7FFFFFFF) ? 1e9f
                                              : sqrtf((float)best) * (1.0f / 96.0f);
        lmax = fmaxf(lmax, pd);
    }

    // block max reduction
    for (int off = 16; off; off >>= 1)
        lmax = fmaxf(lmax, __shfl_xor_sync(0xFFFFFFFFu, lmax, off));
    if (lane == 0) s_red[warp] = lmax;
    __syncthreads();

    if (tid == 0) {
        float bm = s_red[0];
        #pragma unroll
        for (int i = 1; i < NTHR / 32; ++i) bm = fmaxf(bm, s_red[i]);
        g_partials[blk] = bm;
        __threadfence();
        const int prev = atomicAdd(&g_done, 1);
        if (prev == NBLK - 1) s_last = 1;
    }
    __syncthreads();

    // Parallel finisher in the last-arriving block only.
    if (s_last) {
        if (tid < NBLK)
            s_fin[tid] = *(volatile float*)&g_partials[tid];  // 128 parallel loads
        __syncthreads();
        if (tid == 0) {
            float sum = 0.0f;
            #pragma unroll
            for (int nn = 0; nn < NB; ++nn) {
                float dA = -1.0f, dB = -1.0f;
                #pragma unroll
                for (int sl = 0; sl < SLICES; ++sl) {
                    dA = fmaxf(dA, s_fin[(nn * 2 + 0) * SLICES + sl]);
                    dB = fmaxf(dB, s_fin[(nn * 2 + 1) * SLICES + sl]);
                }
                dA = fmaxf(dA, 0.0f);   // empty src set -> 0 (matches reference)
                dB = fmaxf(dB, 0.0f);
                sum += fmaxf(dA, dB);
            }
            out[0] = sum * (1.0f / NB);
            g_done = 0;                  // reset for next graph replay
        }
    }
}

extern "C" void kernel_launch(void* const* d_in, const int* in_sizes, int n_in,
                              void* d_out, int out_size)
{
    (void)in_sizes; (void)n_in; (void)out_size;
    const float* pred = (const float*)d_in[0];
    const float* targ = (const float*)d_in[1];
    hausdorff_kernel<<<NBLK, NTHR>>>(pred, targ, (float*)d_out);
}

// round 3
// speedup vs baseline: 1.9104x; 1.1910x over previous
#include <cuda_runtime.h>
#include <cstdint>

#define HH 96
#define WW 96
#define HW (HH*WW)
#define NB 8
#define SLICES 8
#define NBLK (NB*2*SLICES)       // 128 blocks
#define NTHR 256
#define PTS_PER_BLK (HW/SLICES)  // 1152
#define NWORDS (HH*3)            // 288 mask words per image

__device__ unsigned g_max[NB];   // per-sample hausdorff, float bits (>=0); zero-init, self-reset
__device__ int      g_done = 0;

__device__ __forceinline__ uint32_t pack16(uint32_t x) {
    // x holds one valid low-nibble per byte -> compact to 16 contiguous bits
    x = (x | (x >> 4)) & 0x00FF00FFu;
    return (x | (x >> 8)) & 0x0000FFFFu;
}

__global__ void __launch_bounds__(NTHR)
hausdorff_kernel(const float* __restrict__ pred,
                 const float* __restrict__ targ,
                 float* __restrict__ out)
{
    __shared__ uint32_t s_nib[HW / 16];      // 576 words: one nibble-pair byte per float4
    __shared__ uint32_t s_A[HH * 4];         // stride-4 rows, words 0..2 used
    __shared__ uint32_t s_B[HH * 4];
    __shared__ float    s_red[NTHR / 32];

    const int blk   = blockIdx.x;
    const int slice = blk & (SLICES - 1);
    const int nd    = blk >> 3;              // n*2 + dir
    const int dir   = nd & 1;
    const int n     = nd >> 1;

    const int tid  = threadIdx.x;
    const int lane = tid & 31;
    const int warp = tid >> 5;

    const float4* pA4 = (const float4*)(pred + n * HW);
    const float4* pB4 = (const float4*)(targ + n * HW);

    // ---- Phase 1: coalesced loads, stage 1 byte per float4 (A low nibble, B high)
    // inputs are uniform [0,1): round(x) > 0.5  <=>  x > 0.5f  (0.5 ties round-even to 0)
    uint8_t* nb = (uint8_t*)s_nib;
    #pragma unroll
    for (int k = 0; k < 9; ++k) {
        const int idx4 = tid + k * NTHR;
        const float4 a = pA4[idx4];
        const float4 b = pB4[idx4];
        uint32_t nibA = (a.x > 0.5f ? 1u : 0u) | (a.y > 0.5f ? 2u : 0u)
                      | (a.z > 0.5f ? 4u : 0u) | (a.w > 0.5f ? 8u : 0u);
        uint32_t nibB = (b.x > 0.5f ? 1u : 0u) | (b.y > 0.5f ? 2u : 0u)
                      | (b.z > 0.5f ? 4u : 0u) | (b.w > 0.5f ? 8u : 0u);
        nb[idx4] = (uint8_t)(nibA | (nibB << 4));
    }
    __syncthreads();

    // ---- Phase 2: assemble 32-bit mask words (8 staged bytes each), no atomics
    for (int t = tid; t < NWORDS; t += NTHR) {
        const uint2 w = ((const uint2*)s_nib)[t];      // 8 bytes
        const uint32_t a0 = w.x & 0x0F0F0F0Fu, a1 = w.y & 0x0F0F0F0Fu;
        const uint32_t b0 = (w.x >> 4) & 0x0F0F0F0Fu, b1 = (w.y >> 4) & 0x0F0F0F0Fu;
        const uint32_t wordA = pack16(a0) | (pack16(a1) << 16);
        const uint32_t wordB = pack16(b0) | (pack16(b1) << 16);
        const int row = t / 3;
        const int wi  = row * 4 + (t - row * 3);
        s_A[wi] = wordA;
        s_B[wi] = wordB;
    }
    __syncthreads();

    // dir 0: src = A & ~B, tgt = B;  dir 1: src = B & ~A, tgt = A
    const uint32_t* s_srcp = dir ? s_B : s_A;
    const uint32_t* s_tgt  = dir ? s_A : s_B;

    float lmax = -1.0f;

    const int pend = (slice + 1) * PTS_PER_BLK;
    for (int p = slice * PTS_PER_BLK + tid; p < pend; p += NTHR) {
        const int r = p / WW;
        const int c = p - r * WW;
        const int k0 = c >> 5;
        const uint32_t sw = s_srcp[r * 4 + k0] & ~s_tgt[r * 4 + k0];
        if (!((sw >> (c & 31)) & 1u)) continue;

        int best = 0x7FFFFFFF;                       // squared integer distance
        const int s = c & 31;
        const uint32_t maskR = 0xFFFFFFFFu << s;     // bits >= c within word k0
        const uint32_t maskL = (2u << s) - 1u;       // bits <= c within word k0

        // Expanding ring over rows; exact: row at |dy|=d contributes >= d^2.
        for (int d = 0; d < HH; ++d) {
            const int dd = d * d;
            if (dd >= best) break;
            #pragma unroll
            for (int side = 0; side < 2; ++side) {
                if (side && d == 0) continue;
                const int y = side ? (r + d) : (r - d);
                if ((unsigned)y >= (unsigned)HH) continue;
                const uint32_t* w = &s_tgt[y * 4];

                int dx = 10000;
                uint32_t m = w[k0] & maskR;                          // right side
                if (m) dx = (k0 << 5) + (__ffs(m) - 1) - c;
                else if (k0 < 2 && w[k0 + 1]) dx = ((k0 + 1) << 5) + (__ffs(w[k0 + 1]) - 1) - c;
                else if (k0 < 1 && w[2])      dx = 64 + (__ffs(w[2]) - 1) - c;

                int dl = 10000;                                      // left side
                m = w[k0] & maskL;
                if (m) dl = c - ((k0 << 5) + 31 - __clz(m));
                else if (k0 > 0 && w[k0 - 1]) dl = c - (((k0 - 1) << 5) + 31 - __clz(w[k0 - 1]));
                else if (k0 > 1 && w[0])      dl = c - (31 - __clz(w[0]));

                dx = min(dx, dl);
                if (dx < WW) best = min(best, dd + dx * dx);
            }
        }
        const float pd = (best == 0x7FFFFFFF) ? 1e9f
                                              : sqrtf((float)best) * (1.0f / 96.0f);
        lmax = fmaxf(lmax, pd);
    }

    // block max reduction
    for (int off = 16; off; off >>= 1)
        lmax = fmaxf(lmax, __shfl_xor_sync(0xFFFFFFFFu, lmax, off));
    if (lane == 0) s_red[warp] = lmax;
    __syncthreads();

    if (tid == 0) {
        float bm = s_red[0];
        #pragma unroll
        for (int i = 1; i < NTHR / 32; ++i) bm = fmaxf(bm, s_red[i]);
        bm = fmaxf(bm, 0.0f);   // empty src slice -> 0 (matches reference semantics)
        // per-sample slot: max over both directions and all slices
        atomicMax(&g_max[n], __float_as_uint(bm));   // valid: all values >= 0
        __threadfence();
        const int prev = atomicAdd(&g_done, 1);
        if (prev == NBLK - 1) {
            __threadfence();
            volatile unsigned* gm = g_max;
            float sum = 0.0f;
            #pragma unroll
            for (int i = 0; i < NB; ++i) sum += __uint_as_float(gm[i]);
            out[0] = sum * (1.0f / NB);
            #pragma unroll
            for (int i = 0; i < NB; ++i) gm[i] = 0u;   // reset for next graph replay
            g_done = 0;
        }
    }
}

extern "C" void kernel_launch(void* const* d_in, const int* in_sizes, int n_in,
                              void* d_out, int out_size)
{
    (void)in_sizes; (void)n_in; (void)out_size;
    const float* pred = (const float*)d_in[0];
    const float* targ = (const float*)d_in[1];
    hausdorff_kernel<<<NBLK, NTHR>>>(pred, targ, (float*)d_out);
}